// round 1
// baseline (speedup 1.0000x reference)
#include <cuda_runtime.h>
#include <math.h>

#define A_ 10
#define B_ 1024
#define Y_ 94
#define R_ 256
#define H_ 128
#define G_ 768
#define T_ 50
#define IN_ 350
#define FS_ 0.1f

#define BTILE 74
#define NTILES 14      // 14*74 = 1036 >= 1024
#define ROWPAD 80      // 16 ty * RT 5
#define RT 5
#define HS 257         // padded h row stride (bank-conflict free)
#define YS 96
#define DS 129

// scratch (no cudaMalloc allowed)
__device__ float  g_h[A_ * B_ * R_];   // ~10.5 MB hidden state
__device__ double g_acc[3];            // L, ep, ev

__global__ void init_kernel() {
    const size_t n = (size_t)A_ * B_ * R_;
    for (size_t i = (size_t)blockIdx.x * blockDim.x + threadIdx.x; i < n;
         i += (size_t)gridDim.x * blockDim.x)
        g_h[i] = 0.f;
    if (blockIdx.x == 0 && threadIdx.x < 3) g_acc[threadIdx.x] = 0.0;
}

// ep term is RNN-independent: fully parallel over (t, a, b)
__global__ void ep_kernel(const float* __restrict__ states) {
    int idx = blockIdx.x * blockDim.x + threadIdx.x;
    double e = 0.0;
    if (idx < T_ * A_ * B_) {
        int t = idx / (A_ * B_);
        int r = idx - t * (A_ * B_);
        int a = r >> 10;
        int b = r & 1023;
        size_t base = (((size_t)t * A_ + a) * B_ + b) * Y_ + 4 * a;
        float f0 = states[base + 0], f1 = states[base + 1];
        float f2 = states[base + 2], f3 = states[base + 3];
        size_t base1 = base + (size_t)A_ * B_ * Y_;
        float g0 = states[base1 + 0], g1 = states[base1 + 1];
        float d0 = f0 + f2 * FS_ - g0;
        float d1 = f1 + f3 * FS_ - g1;
        e = sqrt((double)d0 * d0 + (double)d1 * d1);
    }
    #pragma unroll
    for (int o = 16; o; o >>= 1) e += __shfl_down_sync(0xffffffffu, e, o);
    if ((threadIdx.x & 31) == 0) atomicAdd(&g_acc[1], e);
}

__global__ __launch_bounds__(256, 1) void step_kernel(
    const float* __restrict__ states,
    const float* __restrict__ W_ih, const float* __restrict__ W_hh,
    const float* __restrict__ b_ih, const float* __restrict__ b_hh,
    const float* __restrict__ d1w,  const float* __restrict__ d1b,
    const float* __restrict__ d2w,  const float* __restrict__ d2b,
    const float* __restrict__ mw,   const float* __restrict__ mb,
    const float* __restrict__ sw,   const float* __restrict__ sb,
    int t)
{
    extern __shared__ float sm[];
    float* h_s  = sm;                        // ROWPAD*HS
    float* y_s  = h_s + ROWPAD * HS;         // ROWPAD*YS
    float* d_s  = y_s + ROWPAD * YS;         // ROWPAD*DS
    float* e_s  = d_s + ROWPAD * DS;         // ROWPAD*DS
    float* ms_s = e_s + ROWPAD * DS;         // ROWPAD*4

    const int a     = blockIdx.y;
    const int row0  = blockIdx.x * BTILE;
    const int nrows = min(BTILE, B_ - row0);
    const int tid   = threadIdx.x;
    const int tx    = tid & 15;
    const int ty    = tid >> 4;

    // ---- stage h and y_t into smem (zero-fill pad rows: no NaN garbage) ----
    const float* hg = g_h + ((size_t)a * B_ + row0) * R_;
    for (int i = tid; i < ROWPAD * R_; i += 256) {
        int r = i >> 8, k = i & 255;
        h_s[r * HS + k] = (r < nrows) ? hg[(size_t)r * R_ + k] : 0.f;
    }
    const float* yg = states + (((size_t)t * A_ + a) * B_ + row0) * Y_;
    for (int i = tid; i < ROWPAD * Y_; i += 256) {
        int r = i / Y_, k = i - r * Y_;
        y_s[r * YS + k] = (r < nrows) ? yg[(size_t)r * Y_ + k] : 0.f;
    }
    __syncthreads();

    // ---- D1: d = relu(d1_w @ h + d1_b), rows=ty+16i, cols=tx+16jj ----
    {
        float acc[RT][8];
        #pragma unroll
        for (int jj = 0; jj < 8; jj++) {
            float bv = d1b[a * H_ + tx + 16 * jj];
            #pragma unroll
            for (int i = 0; i < RT; i++) acc[i][jj] = bv;
        }
        const float* W = d1w + (size_t)a * H_ * R_;
        for (int k = 0; k < R_; k++) {
            float hv[RT];
            #pragma unroll
            for (int i = 0; i < RT; i++) hv[i] = h_s[(ty + 16 * i) * HS + k];
            #pragma unroll
            for (int jj = 0; jj < 8; jj++) {
                float wv = W[(size_t)(tx + 16 * jj) * R_ + k];
                #pragma unroll
                for (int i = 0; i < RT; i++) acc[i][jj] += hv[i] * wv;
            }
        }
        #pragma unroll
        for (int i = 0; i < RT; i++)
            #pragma unroll
            for (int jj = 0; jj < 8; jj++)
                d_s[(ty + 16 * i) * DS + tx + 16 * jj] = fmaxf(acc[i][jj], 0.f);
    }
    __syncthreads();

    // ---- D2: d = relu(d2_w @ d + d2_b) ----
    {
        float acc[RT][8];
        #pragma unroll
        for (int jj = 0; jj < 8; jj++) {
            float bv = d2b[a * H_ + tx + 16 * jj];
            #pragma unroll
            for (int i = 0; i < RT; i++) acc[i][jj] = bv;
        }
        const float* W = d2w + (size_t)a * H_ * H_;
        for (int k = 0; k < H_; k++) {
            float dv[RT];
            #pragma unroll
            for (int i = 0; i < RT; i++) dv[i] = d_s[(ty + 16 * i) * DS + k];
            #pragma unroll
            for (int jj = 0; jj < 8; jj++) {
                float wv = W[(size_t)(tx + 16 * jj) * H_ + k];
                #pragma unroll
                for (int i = 0; i < RT; i++) acc[i][jj] += dv[i] * wv;
            }
        }
        #pragma unroll
        for (int i = 0; i < RT; i++)
            #pragma unroll
            for (int jj = 0; jj < 8; jj++)
                e_s[(ty + 16 * i) * DS + tx + 16 * jj] = fmaxf(acc[i][jj], 0.f);
    }
    __syncthreads();

    // ---- mean / std heads (4 dots of K=128 per row) ----
    for (int task = tid; task < nrows * 4; task += 256) {
        int r = task >> 2, o = task & 3;
        const float* W = (o < 2) ? (mw + ((size_t)a * 2 + o) * H_)
                                 : (sw + ((size_t)a * 2 + (o - 2)) * H_);
        float acc = (o < 2) ? mb[a * 2 + o] : sb[a * 2 + o - 2];
        for (int k = 0; k < H_; k++) acc += e_s[r * DS + k] * W[k];
        if (o >= 2)  // softplus
            acc = fmaxf(acc, 0.f) + log1pf(expf(-fabsf(acc)));
        ms_s[r * 4 + o] = acc;
    }
    __syncthreads();

    // ---- per-row NLL + ev accumulation ----
    {
        double lsum = 0.0, esum = 0.0;
        if (tid < nrows) {
            int b = row0 + tid;
            size_t xb = (((size_t)(t + 1) * A_ + a) * B_ + b) * Y_ + 4 * a;
            float x0 = states[xb + 2], x1 = states[xb + 3];
            float m0 = ms_s[tid * 4 + 0], m1 = ms_s[tid * 4 + 1];
            float s0 = ms_s[tid * 4 + 2], s1 = ms_s[tid * 4 + 3];
            float z0 = (x0 - m0) / s0, z1 = (x1 - m1) / s1;
            const double L2PI = 1.8378770664093453;
            lsum = 0.5 * ((double)(z0 * z0) + (double)(z1 * z1)
                 + 2.0 * ((double)logf(s0) + (double)logf(s1)) + 2.0 * L2PI);
            float dm0 = m0 - x0, dm1 = m1 - x1;
            esum = sqrt((double)dm0 * dm0 + (double)dm1 * dm1);
        }
        #pragma unroll
        for (int o = 16; o; o >>= 1) {
            lsum += __shfl_down_sync(0xffffffffu, lsum, o);
            esum += __shfl_down_sync(0xffffffffu, esum, o);
        }
        if ((tid & 31) == 0) {
            atomicAdd(&g_acc[0], lsum);
            atomicAdd(&g_acc[2], esum);
        }
    }

    // ---- GRU: gi = W_ih @ [y;h] + b_ih, gh = W_hh @ h + b_hh, update h ----
    const float* Wi = W_ih + (size_t)a * G_ * IN_;
    const float* Wh = W_hh + (size_t)a * G_ * R_;
    for (int jc = 0; jc < 8; jc++) {
        int j0 = jc * 32 + tx;
        float air[RT][2], aiz[RT][2], ain[RT][2];
        float ahr[RT][2], ahz[RT][2], ahn[RT][2];
        #pragma unroll
        for (int jj = 0; jj < 2; jj++) {
            int j = j0 + 16 * jj;
            float bir = b_ih[a * G_ + j];
            float biz = b_ih[a * G_ + 256 + j];
            float bin = b_ih[a * G_ + 512 + j];
            float bhr = b_hh[a * G_ + j];
            float bhz = b_hh[a * G_ + 256 + j];
            float bhn = b_hh[a * G_ + 512 + j];
            #pragma unroll
            for (int i = 0; i < RT; i++) {
                air[i][jj] = bir; aiz[i][jj] = biz; ain[i][jj] = bin;
                ahr[i][jj] = bhr; ahz[i][jj] = bhz; ahn[i][jj] = bhn;
            }
        }
        // y contribution (K = 94)
        for (int k = 0; k < Y_; k++) {
            float yv[RT];
            #pragma unroll
            for (int i = 0; i < RT; i++) yv[i] = y_s[(ty + 16 * i) * YS + k];
            #pragma unroll
            for (int jj = 0; jj < 2; jj++) {
                int j = j0 + 16 * jj;
                float wr = Wi[(size_t)j * IN_ + k];
                float wz = Wi[(size_t)(256 + j) * IN_ + k];
                float wn = Wi[(size_t)(512 + j) * IN_ + k];
                #pragma unroll
                for (int i = 0; i < RT; i++) {
                    air[i][jj] += yv[i] * wr;
                    aiz[i][jj] += yv[i] * wz;
                    ain[i][jj] += yv[i] * wn;
                }
            }
        }
        // h contribution (K = 256) into both gi and gh
        for (int k = 0; k < R_; k++) {
            float hv[RT];
            #pragma unroll
            for (int i = 0; i < RT; i++) hv[i] = h_s[(ty + 16 * i) * HS + k];
            #pragma unroll
            for (int jj = 0; jj < 2; jj++) {
                int j = j0 + 16 * jj;
                float wir = Wi[(size_t)j * IN_ + Y_ + k];
                float wiz = Wi[(size_t)(256 + j) * IN_ + Y_ + k];
                float win = Wi[(size_t)(512 + j) * IN_ + Y_ + k];
                float whr = Wh[(size_t)j * R_ + k];
                float whz = Wh[(size_t)(256 + j) * R_ + k];
                float whn = Wh[(size_t)(512 + j) * R_ + k];
                #pragma unroll
                for (int i = 0; i < RT; i++) {
                    air[i][jj] += hv[i] * wir;
                    aiz[i][jj] += hv[i] * wiz;
                    ain[i][jj] += hv[i] * win;
                    ahr[i][jj] += hv[i] * whr;
                    ahz[i][jj] += hv[i] * whz;
                    ahn[i][jj] += hv[i] * whn;
                }
            }
        }
        // gate combine + in-place h update (block owns these rows exclusively)
        #pragma unroll
        for (int i = 0; i < RT; i++) {
            int r = ty + 16 * i;
            if (r < nrows) {
                #pragma unroll
                for (int jj = 0; jj < 2; jj++) {
                    int j = j0 + 16 * jj;
                    float rg = 1.f / (1.f + expf(-(air[i][jj] + ahr[i][jj])));
                    float zg = 1.f / (1.f + expf(-(aiz[i][jj] + ahz[i][jj])));
                    float ng = tanhf(ain[i][jj] + rg * ahn[i][jj]);
                    float hold = h_s[r * HS + j];
                    float hnew = (1.f - zg) * ng + zg * hold;
                    g_h[((size_t)a * B_ + row0 + r) * R_ + j] = hnew;
                }
            }
        }
    }
}

__global__ void final_kernel(float* out) {
    if (threadIdx.x == 0) {
        const double denom = (double)T_ * A_;
        out[0] = (float)(g_acc[0] / denom);
        out[1] = (float)(g_acc[1] / denom);
        out[2] = (float)(g_acc[2] / denom);
    }
}

extern "C" void kernel_launch(void* const* d_in, const int* in_sizes, int n_in,
                              void* d_out, int out_size) {
    const float* states = (const float*)d_in[0];
    const float* W_ih   = (const float*)d_in[1];
    const float* W_hh   = (const float*)d_in[2];
    const float* b_ih   = (const float*)d_in[3];
    const float* b_hh   = (const float*)d_in[4];
    const float* d1w    = (const float*)d_in[5];
    const float* d1b    = (const float*)d_in[6];
    const float* d2w    = (const float*)d_in[7];
    const float* d2b    = (const float*)d_in[8];
    const float* mw     = (const float*)d_in[9];
    const float* mb     = (const float*)d_in[10];
    const float* sw     = (const float*)d_in[11];
    const float* sb     = (const float*)d_in[12];
    float* out = (float*)d_out;

    const size_t SMEM = (size_t)ROWPAD * (HS + YS + DS + DS + 4) * sizeof(float); // 196,800 B
    cudaFuncSetAttribute(step_kernel, cudaFuncAttributeMaxDynamicSharedMemorySize, (int)SMEM);

    init_kernel<<<256, 256>>>();
    ep_kernel<<<(T_ * A_ * B_ + 255) / 256, 256>>>(states);

    dim3 grid(NTILES, A_);
    for (int t = 0; t < T_; t++) {
        step_kernel<<<grid, 256, SMEM>>>(states, W_ih, W_hh, b_ih, b_hh,
                                         d1w, d1b, d2w, d2b, mw, mb, sw, sb, t);
    }
    final_kernel<<<1, 32>>>(out);
}